// round 16
// baseline (speedup 1.0000x reference)
#include <cuda_runtime.h>
#include <math.h>
#include <stdint.h>

typedef unsigned long long ull;

// Problem constants
#define BB    64
#define CC    512
#define HH    8
#define HD    64
#define FREQE 256
#define ROWS  4096   // B*N == N*M
#define WSLOT (CC * CC)

// ---------------------------------------------------------------------------
// Scratch (device globals; no allocation allowed)
// ---------------------------------------------------------------------------
__device__ float g_pe [ROWS * CC];
__device__ float g_q  [ROWS * CC];
__device__ float g_k  [ROWS * CC];
__device__ float g_v  [ROWS * CC];
__device__ float g_x  [ROWS * CC];
__device__ float g_emb[ROWS * FREQE];
__device__ float g_hid[ROWS * CC];
__device__ float g_bqkv[3 * CC];
__device__ float g_wt [6 * CC * CC];    // transposed W1,W2,Wq,Wk,Wv,Wo (fp32)

__device__ __forceinline__ uint32_t to_tf32(float x) {
    uint32_t u;
    asm("cvt.rna.tf32.f32 %0, %1;" : "=r"(u) : "f"(x));
    return u;
}

__device__ __forceinline__ uint32_t smem_u32(const void* p) {
    uint32_t a;
    asm("{ .reg .u64 t; cvta.to.shared.u64 t, %1; cvt.u32.u64 %0, t; }"
        : "=r"(a) : "l"(p));
    return a;
}

__device__ __forceinline__ void cp16(uint32_t dst, const void* src) {
    asm volatile("cp.async.cg.shared.global [%0], [%1], 16;" :: "r"(dst), "l"(src));
}
#define CP_COMMIT() asm volatile("cp.async.commit_group;" ::: "memory")
#define CP_WAIT(n)  asm volatile("cp.async.wait_group %0;" :: "n"(n) : "memory")

// packed f32x2 helpers (sm_103a)
#define MUL2(o, a, b)    asm("mul.rn.f32x2 %0, %1, %2;"      : "=l"(o) : "l"(a), "l"(b))
#define FMA2(o, a, b, c) asm("fma.rn.f32x2 %0, %1, %2, %3;"  : "=l"(o) : "l"(a), "l"(b), "l"(c))
__device__ __forceinline__ ull pk2(float lo, float hi) {
    ull r; asm("mov.b64 %0, {%1, %2};" : "=l"(r) : "f"(lo), "f"(hi)); return r;
}
__device__ __forceinline__ float sum2(ull a) {
    float lo, hi; asm("mov.b64 {%0, %1}, %2;" : "=f"(lo), "=f"(hi) : "l"(a));
    return lo + hi;
}

// ---------------------------------------------------------------------------
// prep: embedding + 6 weight transposes + fused qkv bias.
// ---------------------------------------------------------------------------
#define PREP_BLOCKS (4096 + 1536 + 6)

__global__ __launch_bounds__(256) void prep_kernel(
    const float* __restrict__ qpos,
    const float* __restrict__ W1, const float* __restrict__ W2,
    const float* __restrict__ Wq, const float* __restrict__ Wk,
    const float* __restrict__ Wv, const float* __restrict__ Wo,
    const float* __restrict__ bq, const float* __restrict__ bv)
{
    int bid = blockIdx.x;
    int t = threadIdx.x;

    if (bid < 4096) {                       // embedding (fast-math)
        int idx = bid * 256 + t;
        int p = idx >> 8;
        int j = idx & 255;
        float tp = qpos[p];
        int jj = j & 127;
        float f = __expf(-9.210340371976184f * (float)jj * (1.0f / 128.0f));
        float a = tp * f;
        float s, c;
        __sincosf(a, &s, &c);
        g_emb[idx] = (j < 128) ? c : s;
        return;
    }
    if (bid < 5632) {                       // weight transposes
        int bid2 = bid - 4096;
        int slot = bid2 >> 8;               // 0..5
        int r    = bid2 & 255;
        int k0 = (r & 15) * 32;
        int n0 = (r >> 4) * 32;
        int K = (slot == 0) ? FREQE : CC;
        if (k0 >= K) return;

        const float* W = (slot == 0) ? W1 : (slot == 1) ? W2 : (slot == 2) ? Wq
                       : (slot == 3) ? Wk : (slot == 4) ? Wv : Wo;

        __shared__ float sm[32][33];
        int tx = t & 31, ty = t >> 5;
#pragma unroll
        for (int i = 0; i < 4; i++) {
            int rr = ty + i * 8;
            sm[rr][tx] = W[(size_t)(k0 + rr) * CC + n0 + tx];
        }
        __syncthreads();
#pragma unroll
        for (int i = 0; i < 4; i++) {
            int rr = ty + i * 8;
            g_wt[(size_t)slot * WSLOT + (size_t)(n0 + rr) * K + k0 + tx] = sm[tx][rr];
        }
        return;
    }
    {                                       // bias fuse
        int i = (bid - 5632) * 256 + t;
        float v = 0.0f;
        if (i < 512) v = bq[i];
        else if (i >= 1024) v = bv[i - 1024];
        g_bqkv[i] = v;
    }
}

// ---------------------------------------------------------------------------
// 1xTF32 GEMM: CTA tile 128x128, BK=32, 4 warps (128 thr), warp tile 64x64.
// ---------------------------------------------------------------------------
#define TPAD 36
#define GTILE (128 * TPAD * 4)          // 18432 B per tile
#define TSMEM (4 * GTILE)               // A,B x 2 stages = 73728 B

#define MMA1688T(d, a, b) \
    asm volatile( \
        "mma.sync.aligned.m16n8k8.row.col.f32.tf32.tf32.f32 " \
        "{%0,%1,%2,%3}, {%4,%5,%6,%7}, {%8,%9}, {%0,%1,%2,%3};" \
        : "+f"((d)[0]), "+f"((d)[1]), "+f"((d)[2]), "+f"((d)[3]) \
        : "r"((a)[0]), "r"((a)[1]), "r"((a)[2]), "r"((a)[3]), \
          "r"((b)[0]), "r"((b)[1]))

__device__ __forceinline__ void gemm_body(
    const float* __restrict__ A, const float* __restrict__ Bt,
    const float* __restrict__ bias, const float* __restrict__ resid,
    float* __restrict__ Cf, float* __restrict__ C2, float* __restrict__ C3,
    int K, int epi, int bx, int by, float* smf)
{
    uint32_t sbase = smem_u32(smf);
    int t = threadIdx.x, lane = t & 31, wid = t >> 5;   // 4 warps
    int wm = wid >> 1;
    int wn = wid & 1;
    int m0 = by * 128, n0 = bx * 128;
    int gr = lane >> 2, gc = lane & 3;

    float acc[4][8][4];
#pragma unroll
    for (int mi = 0; mi < 4; mi++)
#pragma unroll
        for (int ni = 0; ni < 8; ni++)
#pragma unroll
            for (int j = 0; j < 4; j++) acc[mi][ni][j] = 0.0f;

    int nch = K >> 5;

    auto load_chunk = [&](int ch, int buf) {
        int k0 = ch << 5;
#pragma unroll
        for (int i = 0; i < 8; i++) {
            int idx = t + i * 128;
            int row = idx >> 3;
            int c   = idx & 7;
            uint32_t off = (uint32_t)(row * TPAD * 4 + c * 16);
            cp16(sbase + buf * GTILE + off,
                 A + (size_t)(m0 + row) * K + k0 + c * 4);
        }
#pragma unroll
        for (int i = 0; i < 8; i++) {
            int idx = t + i * 128;
            int row = idx >> 3;
            int c   = idx & 7;
            uint32_t off = (uint32_t)(row * TPAD * 4 + c * 16);
            cp16(sbase + 2 * GTILE + buf * GTILE + off,
                 Bt + (size_t)(n0 + row) * K + k0 + c * 4);
        }
        CP_COMMIT();
    };

    load_chunk(0, 0);
    load_chunk(1, 1);

    for (int ch = 0; ch < nch; ch++) {
        if (ch + 1 < nch) { CP_WAIT(1); } else { CP_WAIT(0); }
        __syncthreads();

        int buf = ch & 1;
        const float* sA = smf + (buf * GTILE >> 2);
        const float* sB = smf + ((2 * GTILE + buf * GTILE) >> 2);

#pragma unroll
        for (int ks = 0; ks < 4; ks++) {
            int kk = ks * 8;
            uint32_t af[4][4], bf[8][2];
#pragma unroll
            for (int mi = 0; mi < 4; mi++) {
                int base = (wm * 64 + mi * 16 + gr) * TPAD + kk;
                af[mi][0] = to_tf32(sA[base + gc]);
                af[mi][1] = to_tf32(sA[base + 8 * TPAD + gc]);
                af[mi][2] = to_tf32(sA[base + gc + 4]);
                af[mi][3] = to_tf32(sA[base + 8 * TPAD + gc + 4]);
            }
#pragma unroll
            for (int ni = 0; ni < 8; ni++) {
                int base = (wn * 64 + ni * 8 + gr) * TPAD + kk;
                bf[ni][0] = to_tf32(sB[base + gc]);
                bf[ni][1] = to_tf32(sB[base + gc + 4]);
            }
#pragma unroll
            for (int mi = 0; mi < 4; mi++)
#pragma unroll
                for (int ni = 0; ni < 8; ni++)
                    MMA1688T(acc[mi][ni], af[mi], bf[ni]);
        }
        __syncthreads();
        if (ch + 2 < nch) load_chunk(ch + 2, buf);
    }

#pragma unroll
    for (int mi = 0; mi < 4; mi++) {
#pragma unroll
        for (int ni = 0; ni < 8; ni++) {
            int row0 = m0 + wm * 64 + mi * 16 + gr;
            int col  = n0 + wn * 64 + ni * 8 + gc * 2;
#pragma unroll
            for (int half = 0; half < 2; half++) {
                int row = row0 + half * 8;
                float v0 = acc[mi][ni][half * 2 + 0];
                float v1 = acc[mi][ni][half * 2 + 1];
                if (bias) { v0 += bias[col]; v1 += bias[col + 1]; }
                if (epi == 1) {
                    v0 = v0 / (1.0f + expf(-v0));
                    v1 = v1 / (1.0f + expf(-v1));
                }
                if (epi == 3) {
                    int seg = col >> 9;
                    float* dst = (seg == 0) ? Cf : (seg == 1) ? C2 : C3;
                    size_t o = (size_t)row * CC + (col & 511);
                    *(float2*)(dst + o) = make_float2(v0, v1);
                } else {
                    size_t o = (size_t)row * CC + col;
                    if (epi == 2) {
                        v0 += resid[o];
                        v1 += resid[o + 1];
                    }
                    *(float2*)(Cf + o) = make_float2(v0, v1);
                }
            }
        }
    }
}

__global__ __launch_bounds__(128, 2) void gemm_qkv(const float* __restrict__ query)
{
    extern __shared__ float smf[];
    int bid = blockIdx.x;
    gemm_body(query, g_wt + 2 * WSLOT, g_bqkv, nullptr,
              g_q, g_k, g_v, CC, 3, bid % 12, bid / 12, smf);
}

__global__ __launch_bounds__(128, 2) void gemm_mlp1(const float* __restrict__ b1)
{
    extern __shared__ float smf[];
    int bid = blockIdx.x;
    gemm_body(g_emb, g_wt + 0 * WSLOT, b1, nullptr,
              g_hid, nullptr, nullptr, FREQE, 1, bid & 3, bid >> 2, smf);
}

__global__ __launch_bounds__(128, 2) void gemm_mlp2(const float* __restrict__ b2)
{
    extern __shared__ float smf[];
    int bid = blockIdx.x;
    gemm_body(g_hid, g_wt + 1 * WSLOT, b2, nullptr,
              g_pe, nullptr, nullptr, CC, 0, bid & 3, bid >> 2, smf);
}

__global__ __launch_bounds__(128, 2) void gemm_out(
    const float* __restrict__ bo, const float* __restrict__ query,
    float* __restrict__ out)
{
    extern __shared__ float smf[];
    int bid = blockIdx.x;
    gemm_body(g_x, g_wt + 5 * WSLOT, bo, query,
              out, nullptr, nullptr, CC, 2, bid & 3, bid >> 2, smf);
}

// ---------------------------------------------------------------------------
// Attention: 4 batches/block, 512 threads, 1 CTA/SM, grid (16, 8).
// Phase 1: packed f32x2 math, 2 n-steps per barrier (32 barriers total),
// pe ring x4 with stage-after-wait pairs. Phase 3: packed f32x2 AV.
// ---------------------------------------------------------------------------
#define PROW 80
#define PTL  (64 * PROW)                 // 5120 floats
#define QTL  (64 * 64)                   // 4096 floats
#define SROW 68
#define STL  (64 * SROW)                 // 4352 floats
#define ATTN_SMEM2 ((4 * PTL + 4 * QTL + 4 * STL) * 4)   // 217088 B

__global__ __launch_bounds__(512, 1) void attn_kernel() {
    extern __shared__ float smf[];
    float* pe_sm = smf;                      // [4][PTL]
    float* q_sm  = smf + 4 * PTL;            // [4][QTL]  (Q staging, later V)
    float* s_sm  = smf + 4 * PTL + 4 * QTL;  // [4][STL]

    uint32_t pe_u = smem_u32(pe_sm);
    uint32_t q_u  = smem_u32(q_sm);

    int h  = blockIdx.y;
    int b0 = blockIdx.x * 4;
    int t  = threadIdx.x;

    int bp = t >> 8;          // 0..1 -> batches bp*2, bp*2+1
    int m  = (t >> 2) & 63;
    int dq = t & 3;

    ull kp0[8], kp1[8];       // K packed as d-pairs, batches bp*2 / bp*2+1

    // ---- K staging round A: batches 0,1 -> pe bufs 0,1 ----
#pragma unroll
    for (int i = 0; i < 4; i++) {
        int c = t + i * 512;             // 0..2047
        int b = c >> 10;
        int r = (c >> 4) & 63;
        int j = c & 15;
        cp16(pe_u + (uint32_t)((b * PTL + r * PROW) * 4 + j * 16),
             g_k + ((size_t)((b0 + b) * 64 + r)) * 512 + h * 64 + j * 4);
    }
    CP_COMMIT(); CP_WAIT(0);
    __syncthreads();
    if (bp == 0) {
#pragma unroll
        for (int c = 0; c < 4; c++) {
            float4 k0 = *(const float4*)&pe_sm[0 * PTL + m * PROW + 4 * dq + 16 * c];
            float4 k1 = *(const float4*)&pe_sm[1 * PTL + m * PROW + 4 * dq + 16 * c];
            kp0[2 * c]     = ((ull*)&k0)[0];
            kp0[2 * c + 1] = ((ull*)&k0)[1];
            kp1[2 * c]     = ((ull*)&k1)[0];
            kp1[2 * c + 1] = ((ull*)&k1)[1];
        }
    }
    __syncthreads();

    // ---- K staging round B (batches 2,3) + Q staging (all 4) ----
#pragma unroll
    for (int i = 0; i < 4; i++) {
        int c = t + i * 512;
        int b = c >> 10;
        int r = (c >> 4) & 63;
        int j = c & 15;
        cp16(pe_u + (uint32_t)((b * PTL + r * PROW) * 4 + j * 16),
             g_k + ((size_t)((b0 + 2 + b) * 64 + r)) * 512 + h * 64 + j * 4);
    }
#pragma unroll
    for (int i = 0; i < 8; i++) {
        int c = t + i * 512;             // 0..4095
        int b = c >> 10;
        int r = (c >> 4) & 63;
        int j = c & 15;
        cp16(q_u + (uint32_t)((b * QTL + r * 64) * 4 + j * 16),
             g_q + ((size_t)((b0 + b) * 64 + r)) * 512 + h * 64 + j * 4);
    }
    CP_COMMIT(); CP_WAIT(0);
    __syncthreads();
    if (bp == 1) {
#pragma unroll
        for (int c = 0; c < 4; c++) {
            float4 k0 = *(const float4*)&pe_sm[0 * PTL + m * PROW + 4 * dq + 16 * c];
            float4 k1 = *(const float4*)&pe_sm[1 * PTL + m * PROW + 4 * dq + 16 * c];
            kp0[2 * c]     = ((ull*)&k0)[0];
            kp0[2 * c + 1] = ((ull*)&k0)[1];
            kp1[2 * c]     = ((ull*)&k1)[0];
            kp1[2 * c + 1] = ((ull*)&k1)[1];
        }
    }
    __syncthreads();

    // ---- pe ring staging: buf = n & 3 ----
    auto stage_pe = [&](int n) {
        int buf = n & 3;
#pragma unroll
        for (int i = 0; i < 2; i++) {
            int c = t + i * 512;         // 0..1023
            int r = c >> 4;
            int j = c & 15;
            cp16(pe_u + (uint32_t)((buf * PTL + r * PROW) * 4 + j * 16),
                 g_pe + ((size_t)(n * 64 + r)) * 512 + h * 64 + j * 4);
        }
        CP_COMMIT();
    };
    stage_pe(0);
    stage_pe(1);

    // ---- Phase 1: scores, pairs of n per barrier (32 barriers) ----
    for (int n = 0; n < 64; n += 2) {
        CP_WAIT(0);
        __syncthreads();   // pe[n], pe[n+1] visible; prior readers drained
        if (n + 2 < 64) { stage_pe(n + 2); stage_pe(n + 3); }

#pragma unroll
        for (int u = 0; u < 2; u++) {
            int nn = n + u;
            int buf = nn & 3;
            ull a0 = 0ULL, a1 = 0ULL;    // packed {even,odd} partial sums
            const float* peb = &pe_sm[buf * PTL + m * PROW + 4 * dq];
            const float* qb0 = &q_sm[(bp * 2 + 0) * QTL + nn * 64 + 4 * dq];
            const float* qb1 = &q_sm[(bp * 2 + 1) * QTL + nn * 64 + 4 * dq];
#pragma unroll
            for (int c = 0; c < 4; c++) {
                float4 pe4 = *(const float4*)(peb + 16 * c);
                float4 q0  = *(const float4*)(qb0 + 16 * c);
                float4 q1  = *(const float4*)(qb1 + 16 * c);
                ull pelo = ((ull*)&pe4)[0], pehi = ((ull*)&pe4)[1];
                ull tt;
                MUL2(tt, ((ull*)&q0)[0], kp0[2 * c]);     FMA2(a0, tt, pelo, a0);
                MUL2(tt, ((ull*)&q0)[1], kp0[2 * c + 1]); FMA2(a0, tt, pehi, a0);
                MUL2(tt, ((ull*)&q1)[0], kp1[2 * c]);     FMA2(a1, tt, pelo, a1);
                MUL2(tt, ((ull*)&q1)[1], kp1[2 * c + 1]); FMA2(a1, tt, pehi, a1);
            }
            float p0 = sum2(a0);
            float p1 = sum2(a1);
            p0 += __shfl_xor_sync(0xffffffffu, p0, 1);
            p0 += __shfl_xor_sync(0xffffffffu, p0, 2);
            p1 += __shfl_xor_sync(0xffffffffu, p1, 1);
            p1 += __shfl_xor_sync(0xffffffffu, p1, 2);
            if (dq == 0) {
                s_sm[(bp * 2 + 0) * STL + nn * SROW + m] = p0 * 0.125f;
                s_sm[(bp * 2 + 1) * STL + nn * SROW + m] = p1 * 0.125f;
            }
        }
    }
    __syncthreads();

    // ---- stage V (4 batches) into q_sm ----
#pragma unroll
    for (int i = 0; i < 8; i++) {
        int c = t + i * 512;             // 0..4095
        int b = c >> 10;
        int r = (c >> 4) & 63;
        int j = c & 15;
        cp16(q_u + (uint32_t)((b * QTL + r * 64) * 4 + j * 16),
             g_v + ((size_t)((b0 + b) * 64 + r)) * 512 + h * 64 + j * 4);
    }
    CP_COMMIT();

    // ---- Phase 2: softmax, thread (b, n, half) ----
    {
        int b  = t >> 7;
        int n  = (t >> 1) & 63;
        int hf = t & 1;
        float* row = &s_sm[b * STL + n * SROW + hf * 32];
        float4 e[8];
        float mx = -1e30f;
#pragma unroll
        for (int i = 0; i < 8; i++) {
            e[i] = *(const float4*)(row + i * 4);
            mx = fmaxf(mx, fmaxf(fmaxf(e[i].x, e[i].y), fmaxf(e[i].z, e[i].w)));
        }
        mx = fmaxf(mx, __shfl_xor_sync(0xffffffffu, mx, 1));
        float sum = 0.0f;
#pragma unroll
        for (int i = 0; i < 8; i++) {
            e[i].x = __expf(e[i].x - mx); e[i].y = __expf(e[i].y - mx);
            e[i].z = __expf(e[i].z - mx); e[i].w = __expf(e[i].w - mx);
            sum += e[i].x + e[i].y + e[i].z + e[i].w;
        }
        sum += __shfl_xor_sync(0xffffffffu, sum, 1);
        float inv = 1.0f / sum;
#pragma unroll
        for (int i = 0; i < 8; i++) {
            e[i].x *= inv; e[i].y *= inv; e[i].z *= inv; e[i].w *= inv;
            *(float4*)(row + i * 4) = e[i];
        }
    }

    CP_WAIT(0);
    __syncthreads();

    // ---- Phase 3: AV packed. thread (nh = t>>8, vb = (t>>6)&3, d = t&63) ----
    {
        int nh = t >> 8;
        int vb = (t >> 6) & 3;
        int d  = t & 63;

        ull vp[32];                      // V column packed as m-pairs
#pragma unroll
        for (int mm = 0; mm < 32; mm++)
            vp[mm] = pk2(q_sm[vb * QTL + (2 * mm) * 64 + d],
                         q_sm[vb * QTL + (2 * mm + 1) * 64 + d]);

        int n0 = nh * 32;
        for (int n = n0; n < n0 + 32; n++) {
            const float* sp = &s_sm[vb * STL + n * SROW];
            ull a = 0ULL;
#pragma unroll
            for (int c = 0; c < 16; c++) {
                float4 s4 = *(const float4*)(sp + c * 4);
                FMA2(a, ((ull*)&s4)[0], vp[2 * c], a);
                FMA2(a, ((ull*)&s4)[1], vp[2 * c + 1], a);
            }
            g_x[((size_t)((b0 + vb) * 64 + n)) * 512 + h * 64 + d] = sum2(a);
        }
    }
}

// ---------------------------------------------------------------------------
// Launch — MLP chain on side stream overlapping QKV.
// ---------------------------------------------------------------------------
extern "C" void kernel_launch(void* const* d_in, const int* in_sizes, int n_in,
                              void* d_out, int out_size)
{
    const float* query = (const float*)d_in[0];
    const float* qpos  = (const float*)d_in[1];
    const float* Wq    = (const float*)d_in[2];
    const float* bq    = (const float*)d_in[3];
    const float* Wk    = (const float*)d_in[4];
    const float* Wv    = (const float*)d_in[5];
    const float* bv    = (const float*)d_in[6];
    const float* Wo    = (const float*)d_in[7];
    const float* bo    = (const float*)d_in[8];
    const float* W1    = (const float*)d_in[9];
    const float* b1    = (const float*)d_in[10];
    const float* W2    = (const float*)d_in[11];
    const float* b2    = (const float*)d_in[12];
    float* out = (float*)d_out;

    static cudaStream_t s1 = nullptr;
    static cudaEvent_t ew = nullptr, e1 = nullptr;
    if (!s1) {
        cudaStreamCreateWithFlags(&s1, cudaStreamNonBlocking);
        cudaEventCreateWithFlags(&ew, cudaEventDisableTiming);
        cudaEventCreateWithFlags(&e1, cudaEventDisableTiming);
        cudaFuncSetAttribute(gemm_qkv,  cudaFuncAttributeMaxDynamicSharedMemorySize, TSMEM);
        cudaFuncSetAttribute(gemm_mlp1, cudaFuncAttributeMaxDynamicSharedMemorySize, TSMEM);
        cudaFuncSetAttribute(gemm_mlp2, cudaFuncAttributeMaxDynamicSharedMemorySize, TSMEM);
        cudaFuncSetAttribute(gemm_out,  cudaFuncAttributeMaxDynamicSharedMemorySize, TSMEM);
        cudaFuncSetAttribute(attn_kernel, cudaFuncAttributeMaxDynamicSharedMemorySize, ATTN_SMEM2);
    }

    // prep on main stream
    prep_kernel<<<PREP_BLOCKS, 256>>>(qpos, W1, W2, Wq, Wk, Wv, Wo, bq, bv);
    cudaEventRecord(ew, 0);

    // side stream: pe MLP chain hidden under QKV
    cudaStreamWaitEvent(s1, ew, 0);
    gemm_mlp1<<<128, 128, TSMEM, s1>>>(b1);
    gemm_mlp2<<<128, 128, TSMEM, s1>>>(b2);
    cudaEventRecord(e1, s1);

    // main stream: QKV
    gemm_qkv<<<384, 128, TSMEM>>>(query);

    // join -> attention -> output projection
    cudaStreamWaitEvent(0, e1, 0);
    attn_kernel<<<dim3(16, HH), 512, ATTN_SMEM2>>>();
    gemm_out<<<128, 128, TSMEM>>>(bo, query, out);
}